// round 9
// baseline (speedup 1.0000x reference)
#include <cuda_runtime.h>
#include <cstdint>

// Conv2d 3x3: x[32,128,56,56] f32 * w[256,128,3,3] f32 -> out[32,256,56,56]
// tf32 mma.sync implicit GEMM. CTA: M=256 oc x N=64 flat px, K=1152 (72 k16 chunks).
// Round-6 structure (proven 367us) + A fragments moved from per-step LDG.128 (L2 latency)
// into the same 4-stage cp.async ring as B, consumed via conflict-free LDS.128.

static __device__ __forceinline__ uint32_t smem_u32(const void* p) {
    uint32_t a;
    asm("{ .reg .u64 t; cvta.to.shared.u64 t, %1; cvt.u32.u64 %0, t; }" : "=r"(a) : "l"(p));
    return a;
}
static __device__ __forceinline__ uint32_t totf(float f) {
    float r; asm("cvt.rna.tf32.f32 %0, %1;" : "=f"(r) : "f"(f));
    return __float_as_uint(r);
}

#define LDSM4(r, addr) \
    asm volatile("ldmatrix.sync.aligned.m8n8.x4.shared.b16 {%0,%1,%2,%3}, [%4];" \
        : "=r"((r)[0]), "=r"((r)[1]), "=r"((r)[2]), "=r"((r)[3]) : "r"(addr))

#define MMA1688(d, a, b0, b1) \
    asm volatile("mma.sync.aligned.m16n8k8.row.col.f32.tf32.tf32.f32 " \
        "{%0,%1,%2,%3}, {%4,%5,%6,%7}, {%8,%9}, {%0,%1,%2,%3};" \
        : "+f"((d)[0]), "+f"((d)[1]), "+f"((d)[2]), "+f"((d)[3]) \
        : "r"((a)[0]), "r"((a)[1]), "r"((a)[2]), "r"((a)[3]), "r"(b0), "r"(b1))

#define LDS128(r, addr) \
    asm volatile("ld.shared.v4.b32 {%0,%1,%2,%3}, [%4];" \
        : "=r"((r)[0]), "=r"((r)[1]), "=r"((r)[2]), "=r"((r)[3]) : "r"(addr))

static __device__ __forceinline__ void cpa4(uint32_t dst, const float* src, int ok) {
    asm volatile(
        "{\n\t.reg .pred p;\n\t.reg .b32 sz;\n\t"
        "setp.ne.b32 p, %2, 0;\n\t"
        "selp.b32 sz, 4, 0, p;\n\t"
        "cp.async.ca.shared.global [%0], [%1], 4, sz;\n\t}"
        :: "r"(dst), "l"(src), "r"(ok) : "memory");
}
static __device__ __forceinline__ void cpa16u(uint32_t dst, const float* src) {
    asm volatile("cp.async.ca.shared.global [%0], [%1], 16;"
        :: "r"(dst), "l"(src) : "memory");
}
#define CP_COMMIT() asm volatile("cp.async.commit_group;" ::: "memory")
#define CP_WAIT2()  asm volatile("cp.async.wait_group 2;"  ::: "memory")

#define ROWB 80u               // B smem row stride bytes
#define BTILE (64u * ROWB)     // 5120 B per B stage
#define ASTAGE 16384u          // 16 KB per A stage (2 k8-steps x 16 oc16 x 32 lanes x 16B)
#define A_BYTES (4u * ASTAGE)  // 65536
#define DSMEM (A_BYTES + 4u * BTILE)   // 86016

// A fragments: [kb(144)][oc16(16)][lane(32)][4], tf32 bits, ldmatrix.x4 reg order.
__device__ float g_prep[144 * 16 * 32 * 4];
// x pre-rounded to tf32 bits.
__device__ float g_xtf[32 * 128 * 56 * 56];

__global__ void __launch_bounds__(256)
prep_weights(const float* __restrict__ w) {
    int idx  = blockIdx.x * 256 + threadIdx.x;
    int j    = idx & 3;
    int lane = (idx >> 2) & 31;
    int oc16 = (idx >> 7) & 15;
    int kb   = idx >> 11;
    int row  = oc16 * 16 + (lane >> 2) + ((j & 1) ? 8 : 0);
    int col  = kb * 8 + (lane & 3) + ((j & 2) ? 4 : 0);
    g_prep[idx] = __uint_as_float(totf(w[(size_t)row * 1152 + col]));
}

__global__ void __launch_bounds__(256)
prep_x(const float* __restrict__ x) {
    size_t i = ((size_t)blockIdx.x * 256 + threadIdx.x) * 4;
    float4 v = *reinterpret_cast<const float4*>(x + i);
    float4 o;
    o.x = __uint_as_float(totf(v.x));
    o.y = __uint_as_float(totf(v.y));
    o.z = __uint_as_float(totf(v.z));
    o.w = __uint_as_float(totf(v.w));
    *reinterpret_cast<float4*>(g_xtf + i) = o;
}

extern __shared__ float dynsm[];

__global__ void __launch_bounds__(256, 2)
conv3x3_tf32_hmma6(float* __restrict__ out)
{
    __shared__ int s_tbl[1152];

    const int tid  = threadIdx.x;
    const int lane = tid & 31;
    const int wid  = tid >> 5;
    const int warpM = wid & 3;            // 64 oc each
    const int warpN = wid >> 2;           // 32 px each

    const int gp0 = blockIdx.x << 6;

    for (int k = tid; k < 1152; k += 256) {
        int ic = k / 9;
        int r9 = k - ic * 9;
        int kh = r9 / 3;
        int kw = r9 - kh * 3;
        s_tbl[k] = (((ic * 3136) + (kh - 1) * 56 + (kw - 1)) << 4) | r9;
    }

    // ---- B staging geometry (round-6): warp = 32 consecutive px, one k-quad ----
    const int pl   = ((wid & 1) << 5) + lane;
    const int quad = wid >> 1;
    const int gp   = gp0 + pl;
    const int img  = gp / 3136;
    const int p    = gp - img * 3136;
    const int r    = p / 56;
    const int c    = p - r * 56;
    unsigned mask9 = 0;
    #pragma unroll
    for (int dh = -1; dh <= 1; dh++)
        #pragma unroll
        for (int dw = -1; dw <= 1; dw++)
            if ((unsigned)(r + dh) < 56u && (unsigned)(c + dw) < 56u)
                mask9 |= 1u << ((dh + 1) * 3 + (dw + 1));
    const float* pbase = g_xtf + (size_t)img * 401408 + p;

    const uint32_t aS = smem_u32(dynsm);                      // A ring: 64 KB
    const uint32_t bS = aS + A_BYTES;                         // B ring: 20 KB
    const uint32_t sts_off = (uint32_t)pl * ROWB + (uint32_t)(quad << 4);
    const uint32_t boff = (uint32_t)((warpN << 5) + (lane & 7) + ((lane >> 4) << 3)) * ROWB
                        + (uint32_t)(((lane >> 3) & 1) << 4);

    // A staging: chunk ch = contiguous 1024 x 16B at g_prep + ch*4096 floats.
    const float* aSrc = g_prep + (size_t)tid * 4;             // + ch*4096 + t*1024
    const uint32_t aDst = aS + (uint32_t)tid * 16u;           // + (ch&3)*ASTAGE + t*4096
    // A consumption: per step s, tile i: stage + s*8192 + (warpM*4+i)*512 + lane*16
    const uint32_t aCon = aS + (uint32_t)(warpM * 4) * 512u + (uint32_t)lane * 16u;

    float acc[4][4][4];
    #pragma unroll
    for (int i = 0; i < 4; i++)
        #pragma unroll
        for (int j = 0; j < 4; j++)
            #pragma unroll
            for (int q = 0; q < 4; q++) acc[i][j][q] = 0.0f;

    __syncthreads();   // table ready

    // ---- prologue: stage chunks 0..2 (A + B in one group each) ----
    #pragma unroll
    for (int pre = 0; pre < 3; pre++) {
        #pragma unroll
        for (int t = 0; t < 4; t++)
            cpa16u(aDst + (uint32_t)(pre * ASTAGE) + (uint32_t)(t * 4096),
                   aSrc + (size_t)pre * 4096 + t * 1024);
        int4 e = *reinterpret_cast<const int4*>(&s_tbl[pre * 16 + (quad << 2)]);
        uint32_t d = bS + (uint32_t)pre * BTILE + sts_off;
        int ee[4] = {e.x, e.y, e.z, e.w};
        #pragma unroll
        for (int j = 0; j < 4; j++) {
            int ok = (mask9 >> (ee[j] & 15)) & 1;
            cpa4(d + 4u * j, pbase + (ok ? (ee[j] >> 4) : 0), ok);
        }
        CP_COMMIT();
    }

    #pragma unroll 1
    for (int ch = 0; ch < 72; ch++) {
        CP_WAIT2();
        __syncthreads();

        // ---- stage chunk ch+3 ----
        if (ch + 3 < 72) {
            #pragma unroll
            for (int t = 0; t < 4; t++)
                cpa16u(aDst + (uint32_t)(((ch + 3) & 3) * ASTAGE) + (uint32_t)(t * 4096),
                       aSrc + (size_t)(ch + 3) * 4096 + t * 1024);
            int4 e = *reinterpret_cast<const int4*>(&s_tbl[(ch + 3) * 16 + (quad << 2)]);
            uint32_t d = bS + (uint32_t)(((ch + 3) & 3) * BTILE) + sts_off;
            int ee[4] = {e.x, e.y, e.z, e.w};
            #pragma unroll
            for (int j = 0; j < 4; j++) {
                int ok = (mask9 >> (ee[j] & 15)) & 1;
                cpa4(d + 4u * j, pbase + (ok ? (ee[j] >> 4) : 0), ok);
            }
        }
        CP_COMMIT();

        // ---- compute: 2 k8 steps, A and B both from smem ----
        const uint32_t bBuf = bS + (uint32_t)((ch & 3) * BTILE);
        const uint32_t aBuf = aCon + (uint32_t)((ch & 3) * ASTAGE);
        #pragma unroll
        for (int s = 0; s < 2; s++) {
            uint32_t af[4][4];
            #pragma unroll
            for (int i = 0; i < 4; i++)
                LDS128(af[i], aBuf + (uint32_t)(s * 8192 + i * 512));
            uint32_t bf[2][4];
            #pragma unroll
            for (int jj = 0; jj < 2; jj++)
                LDSM4(bf[jj], bBuf + boff + (uint32_t)(jj * 16) * ROWB + (uint32_t)(s * 32));
            #pragma unroll
            for (int i = 0; i < 4; i++)
                #pragma unroll
                for (int j = 0; j < 4; j++)
                    MMA1688(acc[i][j], af[i], bf[j >> 1][(j & 1) * 2], bf[j >> 1][(j & 1) * 2 + 1]);
        }
    }

    // ---- epilogue: STG.64 per fragment pair ----
    #pragma unroll
    for (int i = 0; i < 4; i++) {
        const int mrow = warpM * 64 + i * 16 + (lane >> 2);
        #pragma unroll
        for (int j = 0; j < 4; j++) {
            int nl  = warpN * 32 + j * 8 + 2 * (lane & 3);
            int gp2 = gp0 + nl;
            int im2 = gp2 / 3136;
            int pp  = gp2 - im2 * 3136;
            float* o0 = out + ((size_t)im2 * 256 + mrow) * 3136 + pp;
            *reinterpret_cast<float2*>(o0)            = make_float2(acc[i][j][0], acc[i][j][1]);
            *reinterpret_cast<float2*>(o0 + 8 * 3136) = make_float2(acc[i][j][2], acc[i][j][3]);
        }
    }
}

extern "C" void kernel_launch(void* const* d_in, const int* in_sizes, int n_in,
                              void* d_out, int out_size) {
    const float* x = (const float*)d_in[0];   // [32,128,56,56]
    const float* w = (const float*)d_in[1];   // [256,128,3,3]
    float* out = (float*)d_out;               // [32,256,56,56]

    prep_weights<<<1152, 256>>>(w);
    prep_x<<<12544, 256>>>(x);
    cudaFuncSetAttribute(conv3x3_tf32_hmma6,
                         cudaFuncAttributeMaxDynamicSharedMemorySize, DSMEM);
    conv3x3_tf32_hmma6<<<1568, 256, DSMEM>>>(out);
}

// round 10
// speedup vs baseline: 1.1511x; 1.1511x over previous
#include <cuda_runtime.h>
#include <cstdint>

// Conv2d 3x3: x[32,128,56,56] f32 * w[256,128,3,3] f32 -> out[32,256,56,56]
// tf32 mma.sync implicit GEMM. CTA: M=256 oc x N=64 flat px, K=1152 (72 k16 chunks).
// Round-6 structure (proven 367us) with ONE change: 2 chunks per barrier
// (6-stage B ring, wait_group 2 + syncthreads per chunk PAIR, 36 barriers not 72).
// A: fragment-packed tf32 in gmem, LDG.128 + register ping-pong.
// B: 4B zfill cp.async im2col staging, LDSM consumption.

static __device__ __forceinline__ uint32_t smem_u32(const void* p) {
    uint32_t a;
    asm("{ .reg .u64 t; cvta.to.shared.u64 t, %1; cvt.u32.u64 %0, t; }" : "=r"(a) : "l"(p));
    return a;
}
static __device__ __forceinline__ uint32_t totf(float f) {
    float r; asm("cvt.rna.tf32.f32 %0, %1;" : "=f"(r) : "f"(f));
    return __float_as_uint(r);
}

#define LDSM4(r, addr) \
    asm volatile("ldmatrix.sync.aligned.m8n8.x4.shared.b16 {%0,%1,%2,%3}, [%4];" \
        : "=r"((r)[0]), "=r"((r)[1]), "=r"((r)[2]), "=r"((r)[3]) : "r"(addr))

#define MMA1688(d, a, b0, b1) \
    asm volatile("mma.sync.aligned.m16n8k8.row.col.f32.tf32.tf32.f32 " \
        "{%0,%1,%2,%3}, {%4,%5,%6,%7}, {%8,%9}, {%0,%1,%2,%3};" \
        : "+f"((d)[0]), "+f"((d)[1]), "+f"((d)[2]), "+f"((d)[3]) \
        : "r"((a)[0]), "r"((a)[1]), "r"((a)[2]), "r"((a)[3]), "r"(b0), "r"(b1))

static __device__ __forceinline__ void cpa4(uint32_t dst, const float* src, int ok) {
    asm volatile(
        "{\n\t.reg .pred p;\n\t.reg .b32 sz;\n\t"
        "setp.ne.b32 p, %2, 0;\n\t"
        "selp.b32 sz, 4, 0, p;\n\t"
        "cp.async.ca.shared.global [%0], [%1], 4, sz;\n\t}"
        :: "r"(dst), "l"(src), "r"(ok) : "memory");
}
#define CP_COMMIT() asm volatile("cp.async.commit_group;" ::: "memory")
#define CP_WAIT2()  asm volatile("cp.async.wait_group 2;"  ::: "memory")

#define ROWB 80u              // B smem row stride (16 k * 4B + pad)
#define BTILE (64u * ROWB)    // 5120 B per stage
#define NSTAGE 6

// A fragments: [kb(144)][oc16(16)][lane(32)][4], tf32 bits, ldmatrix.x4 reg order.
__device__ float g_prep[144 * 16 * 32 * 4];
// x pre-rounded to tf32 bits (zero-mean rounding preserved through cp.async).
__device__ float g_xtf[32 * 128 * 56 * 56];

__global__ void __launch_bounds__(256)
prep_weights(const float* __restrict__ w) {
    int idx  = blockIdx.x * 256 + threadIdx.x;
    int j    = idx & 3;
    int lane = (idx >> 2) & 31;
    int oc16 = (idx >> 7) & 15;
    int kb   = idx >> 11;
    int row  = oc16 * 16 + (lane >> 2) + ((j & 1) ? 8 : 0);
    int col  = kb * 8 + (lane & 3) + ((j & 2) ? 4 : 0);
    g_prep[idx] = __uint_as_float(totf(w[(size_t)row * 1152 + col]));
}

__global__ void __launch_bounds__(256)
prep_x(const float* __restrict__ x) {
    size_t i = ((size_t)blockIdx.x * 256 + threadIdx.x) * 4;
    float4 v = *reinterpret_cast<const float4*>(x + i);
    float4 o;
    o.x = __uint_as_float(totf(v.x));
    o.y = __uint_as_float(totf(v.y));
    o.z = __uint_as_float(totf(v.z));
    o.w = __uint_as_float(totf(v.w));
    *reinterpret_cast<float4*>(g_xtf + i) = o;
}

__global__ void __launch_bounds__(256, 2)
conv3x3_tf32_hmma7(float* __restrict__ out)
{
    __shared__ int   s_tbl[1152];
    __shared__ float s_B[NSTAGE][64 * 20];   // 6 x 5120 B

    const int tid  = threadIdx.x;
    const int lane = tid & 31;
    const int wid  = tid >> 5;
    const int warpM = wid & 3;            // 64 oc each
    const int warpN = wid >> 2;           // 32 px each

    const int gp0 = blockIdx.x << 6;

    for (int k = tid; k < 1152; k += 256) {
        int ic = k / 9;
        int r9 = k - ic * 9;
        int kh = r9 / 3;
        int kw = r9 - kh * 3;
        s_tbl[k] = (((ic * 3136) + (kh - 1) * 56 + (kw - 1)) << 4) | r9;
    }

    // ---- B staging geometry: warp = 32 consecutive px, one k-quad ----
    const int pl   = ((wid & 1) << 5) + lane;
    const int quad = wid >> 1;
    const int gp   = gp0 + pl;
    const int img  = gp / 3136;
    const int p    = gp - img * 3136;
    const int r    = p / 56;
    const int c    = p - r * 56;
    unsigned mask9 = 0;
    #pragma unroll
    for (int dh = -1; dh <= 1; dh++)
        #pragma unroll
        for (int dw = -1; dw <= 1; dw++)
            if ((unsigned)(r + dh) < 56u && (unsigned)(c + dw) < 56u)
                mask9 |= 1u << ((dh + 1) * 3 + (dw + 1));
    const float* pbase = g_xtf + (size_t)img * 401408 + p;

    const uint32_t bS = smem_u32(s_B[0]);
    const uint32_t sts_off = (uint32_t)pl * ROWB + (uint32_t)(quad << 4);
    const uint32_t boff = (uint32_t)((warpN << 5) + (lane & 7) + ((lane >> 4) << 3)) * ROWB
                        + (uint32_t)(((lane >> 3) & 1) << 4);

    const float4* aP = reinterpret_cast<const float4*>(g_prep) + (size_t)(warpM * 4) * 32 + lane;

    float acc[4][4][4];
    #pragma unroll
    for (int i = 0; i < 4; i++)
        #pragma unroll
        for (int j = 0; j < 4; j++)
            #pragma unroll
            for (int q = 0; q < 4; q++) acc[i][j][q] = 0.0f;

    __syncthreads();   // table ready

    // ---- prologue: stage chunks 0..3 into buffers 0..3 ----
    #pragma unroll
    for (int pre = 0; pre < 4; pre++) {
        int4 e = *reinterpret_cast<const int4*>(&s_tbl[pre * 16 + (quad << 2)]);
        uint32_t d = bS + (uint32_t)pre * BTILE + sts_off;
        int ee[4] = {e.x, e.y, e.z, e.w};
        #pragma unroll
        for (int j = 0; j < 4; j++) {
            int ok = (mask9 >> (ee[j] & 15)) & 1;
            cpa4(d + 4u * j, pbase + (ok ? (ee[j] >> 4) : 0), ok);
        }
        CP_COMMIT();
    }

    // ---- prologue: A regs for kb=0 ----
    uint32_t af[2][4][4];
    #pragma unroll
    for (int i = 0; i < 4; i++) {
        float4 av = __ldg(aP + (size_t)i * 32);
        af[0][i][0] = __float_as_uint(av.x); af[0][i][1] = __float_as_uint(av.y);
        af[0][i][2] = __float_as_uint(av.z); af[0][i][3] = __float_as_uint(av.w);
    }

    // ---- main: 12 groups x 3 macro-steps x 2 chunks; ring indices compile-time ----
    #pragma unroll 1
    for (int cg = 0; cg < 12; cg++) {
        #pragma unroll
        for (int t = 0; t < 3; t++) {
            const int ch = cg * 6 + t * 2;
            const int b0 = 2 * t;
            const int b1 = 2 * t + 1;
            const int b4 = (2 * t + 4) % NSTAGE;
            const int b5 = (2 * t + 5) % NSTAGE;

            CP_WAIT2();
            __syncthreads();

            // stage chunks ch+4, ch+5 (their buffers were consumed last macro-step)
            if (ch + 4 < 72) {
                int4 e = *reinterpret_cast<const int4*>(&s_tbl[(ch + 4) * 16 + (quad << 2)]);
                uint32_t d = bS + (uint32_t)b4 * BTILE + sts_off;
                int ee[4] = {e.x, e.y, e.z, e.w};
                #pragma unroll
                for (int j = 0; j < 4; j++) {
                    int ok = (mask9 >> (ee[j] & 15)) & 1;
                    cpa4(d + 4u * j, pbase + (ok ? (ee[j] >> 4) : 0), ok);
                }
            }
            CP_COMMIT();
            if (ch + 5 < 72) {
                int4 e = *reinterpret_cast<const int4*>(&s_tbl[(ch + 5) * 16 + (quad << 2)]);
                uint32_t d = bS + (uint32_t)b5 * BTILE + sts_off;
                int ee[4] = {e.x, e.y, e.z, e.w};
                #pragma unroll
                for (int j = 0; j < 4; j++) {
                    int ok = (mask9 >> (ee[j] & 15)) & 1;
                    cpa4(d + 4u * j, pbase + (ok ? (ee[j] >> 4) : 0), ok);
                }
            }
            CP_COMMIT();

            // ---- compute 2 chunks = 4 k8 steps, A ping-pong prefetch ----
            #pragma unroll
            for (int s = 0; s < 4; s++) {
                const int kb  = ch * 2 + s;
                const int cur = kb & 1;
                if (kb + 1 < 144) {
                    #pragma unroll
                    for (int i = 0; i < 4; i++) {
                        float4 av = __ldg(aP + ((size_t)(kb + 1) * 16 + i) * 32);
                        af[cur ^ 1][i][0] = __float_as_uint(av.x);
                        af[cur ^ 1][i][1] = __float_as_uint(av.y);
                        af[cur ^ 1][i][2] = __float_as_uint(av.z);
                        af[cur ^ 1][i][3] = __float_as_uint(av.w);
                    }
                }
                const uint32_t bBuf = bS + (uint32_t)((s < 2) ? b0 : b1) * BTILE;
                uint32_t bf[2][4];
                #pragma unroll
                for (int jj = 0; jj < 2; jj++)
                    LDSM4(bf[jj], bBuf + boff + (uint32_t)(jj * 16) * ROWB
                                       + (uint32_t)((s & 1) * 32));
                #pragma unroll
                for (int i = 0; i < 4; i++)
                    #pragma unroll
                    for (int j = 0; j < 4; j++)
                        MMA1688(acc[i][j], af[cur][i],
                                bf[j >> 1][(j & 1) * 2], bf[j >> 1][(j & 1) * 2 + 1]);
            }
        }
    }

    // ---- epilogue: STG.64 per fragment pair ----
    #pragma unroll
    for (int i = 0; i < 4; i++) {
        const int mrow = warpM * 64 + i * 16 + (lane >> 2);
        #pragma unroll
        for (int j = 0; j < 4; j++) {
            int nl  = warpN * 32 + j * 8 + 2 * (lane & 3);
            int gp2 = gp0 + nl;
            int im2 = gp2 / 3136;
            int pp  = gp2 - im2 * 3136;
            float* o0 = out + ((size_t)im2 * 256 + mrow) * 3136 + pp;
            *reinterpret_cast<float2*>(o0)            = make_float2(acc[i][j][0], acc[i][j][1]);
            *reinterpret_cast<float2*>(o0 + 8 * 3136) = make_float2(acc[i][j][2], acc[i][j][3]);
        }
    }
}

extern "C" void kernel_launch(void* const* d_in, const int* in_sizes, int n_in,
                              void* d_out, int out_size) {
    const float* x = (const float*)d_in[0];   // [32,128,56,56]
    const float* w = (const float*)d_in[1];   // [256,128,3,3]
    float* out = (float*)d_out;               // [32,256,56,56]

    prep_weights<<<1152, 256>>>(w);
    prep_x<<<12544, 256>>>(x);
    conv3x3_tf32_hmma7<<<1568, 256>>>(out);
}